// round 11
// baseline (speedup 1.0000x reference)
#include <cuda_runtime.h>

// Per-node collapsed features (A, B, T, pad). 100000 nodes max.
#define MAX_NODES 100352
__device__ float4 g_node[MAX_NODES];

// Generation-based grid barrier state. Works across CUDA-graph replays:
// g_count returns to 0 after each barrier; g_release only advances.
__device__ unsigned g_count = 0;
__device__ unsigned g_release = 0;

#define NBLOCKS 888          // 148 SMs x 6 blocks — residency guaranteed by launch_bounds
#define NTHREADS 256

// ---------------------------------------------------------------------------
// Single persistent kernel.
// Phase 1 (nodes, grid-stride):
//   h0 = x·W1[:,0]+b1[0]; h1 = x·W1[:,1]+b1[1]; T = x·g + gb
//   A = w0*h0 + w1*h1;  B = w1*h0 - w0*h1
//   g_node[i] = (A,B,T);  out[i] = A + T + bout      (plain store — no memset!)
// Grid barrier (all 888 blocks resident).
// Phase 2 (edges, grid-stride), edge (u,v), phase p, c=cos p, s=sin p:
//   out[v] += c*A_u + s*B_u + T_u
//   out[u] += c*A_v - s*B_v + T_v
// ---------------------------------------------------------------------------
__global__ void __launch_bounds__(NTHREADS, 6)
sheaf_kernel(const float4* __restrict__ x4,
             const int2* __restrict__ edges,
             const float* __restrict__ phases,
             const float* __restrict__ W1,
             const float* __restrict__ b1,
             const float* __restrict__ Wout,
             const float* __restrict__ bout,
             float* __restrict__ out, int n, int m, int hidden) {
    // Snapshot barrier generation BEFORE any arrival can happen this launch.
    unsigned gen = *(volatile unsigned*)&g_release;

    int lane = threadIdx.x & 31;
    int gtid = blockIdx.x * NTHREADS + threadIdx.x;
    const int gsz = NBLOCKS * NTHREADS;

    // ---- constant precompute: warp-redundant shuffle reduce (hot L1 lines)
    float g0 = 0.f, g1 = 0.f, g2 = 0.f, g3 = 0.f, gbs = 0.f;
    for (int t = lane; t < hidden; t += 32) {
        float wk = __ldg(Wout + t);
        float mask = (t >= 2) ? wk : 0.f;
        g0  = fmaf(mask, __ldg(W1 + 0 * hidden + t), g0);
        g1  = fmaf(mask, __ldg(W1 + 1 * hidden + t), g1);
        g2  = fmaf(mask, __ldg(W1 + 2 * hidden + t), g2);
        g3  = fmaf(mask, __ldg(W1 + 3 * hidden + t), g3);
        gbs = fmaf(mask, __ldg(b1 + t), gbs);
    }
    #pragma unroll
    for (int off = 16; off > 0; off >>= 1) {
        g0  += __shfl_xor_sync(0xFFFFFFFF, g0, off);
        g1  += __shfl_xor_sync(0xFFFFFFFF, g1, off);
        g2  += __shfl_xor_sync(0xFFFFFFFF, g2, off);
        g3  += __shfl_xor_sync(0xFFFFFFFF, g3, off);
        gbs += __shfl_xor_sync(0xFFFFFFFF, gbs, off);
    }

    {   // ---- phase 1: per-node collapse + base store
        float w0  = __ldg(Wout + 0), w1 = __ldg(Wout + 1);
        float a0  = __ldg(W1 + 0 * hidden),     a1 = __ldg(W1 + 1 * hidden);
        float a2  = __ldg(W1 + 2 * hidden),     a3 = __ldg(W1 + 3 * hidden);
        float d0  = __ldg(W1 + 0 * hidden + 1), d1 = __ldg(W1 + 1 * hidden + 1);
        float d2  = __ldg(W1 + 2 * hidden + 1), d3 = __ldg(W1 + 3 * hidden + 1);
        float b10 = __ldg(b1 + 0), b11 = __ldg(b1 + 1);
        float bo  = __ldg(bout);

        for (int i = gtid; i < n; i += gsz) {
            float4 xv = x4[i];
            float h0 = fmaf(xv.x, a0, fmaf(xv.y, a1, fmaf(xv.z, a2, fmaf(xv.w, a3, b10))));
            float h1 = fmaf(xv.x, d0, fmaf(xv.y, d1, fmaf(xv.z, d2, fmaf(xv.w, d3, b11))));
            float T  = fmaf(xv.x, g0, fmaf(xv.y, g1, fmaf(xv.z, g2, fmaf(xv.w, g3, gbs))));
            float A  = fmaf(h0, w0, h1 * w1);
            float B  = fmaf(h0, w1, -h1 * w0);
            g_node[i] = make_float4(A, B, T, 0.f);
            out[i] = A + T + bo;      // plain store — edge atomics come after barrier
        }
    }

    // ---- grid barrier (all NBLOCKS resident by construction)
    __threadfence();                  // publish phase-1 writes
    __syncthreads();
    if (threadIdx.x == 0) {
        unsigned t = atomicAdd(&g_count, 1);
        if (t == NBLOCKS - 1) {
            g_count = 0;              // reset for next replay
            __threadfence();
            atomicAdd(&g_release, 1); // release this generation
        } else {
            while (*(volatile unsigned*)&g_release == gen) __nanosleep(40);
        }
    }
    __syncthreads();
    __threadfence();                  // acquire phase-1 writes from other blocks

    // ---- phase 2: edges (light body — the measured 21.5us configuration)
    for (int e = gtid; e < m; e += gsz) {
        int2 ed = edges[e];
        float p = phases[e];
        float s, c;
        __sincosf(p, &s, &c);
        float4 nu = __ldg(&g_node[ed.x]);
        float4 nv = __ldg(&g_node[ed.y]);
        atomicAdd(out + ed.y, fmaf(c, nu.x, fmaf(s,  nu.y, nu.z)));
        atomicAdd(out + ed.x, fmaf(c, nv.x, fmaf(-s, nv.y, nv.z)));
    }
}

extern "C" void kernel_launch(void* const* d_in, const int* in_sizes, int n_in,
                              void* d_out, int out_size) {
    const float* x      = (const float*)d_in[0];
    const int*   edges  = (const int*)  d_in[1];
    const float* W1     = (const float*)d_in[2];
    const float* b1     = (const float*)d_in[3];
    const float* phases = (const float*)d_in[4];
    const float* Wout   = (const float*)d_in[5];
    const float* bout   = (const float*)d_in[6];
    float* out = (float*)d_out;

    int hidden = in_sizes[3];          // 64
    int n = in_sizes[0] / 4;           // nodes (IN_DIM = 4)
    int m = in_sizes[1] / 2;           // edges

    sheaf_kernel<<<NBLOCKS, NTHREADS>>>((const float4*)x,
                                        (const int2*)edges, phases,
                                        W1, b1, Wout, bout,
                                        out, n, m, hidden);
}

// round 13
// speedup vs baseline: 1.1767x; 1.1767x over previous
#include <cuda_runtime.h>

// Scratch: per-node collapsed features (A, B, T, pad). 100000 nodes max.
#define MAX_NODES 100352
__device__ float4 g_node[MAX_NODES];

// ---------------------------------------------------------------------------
// node_kernel: warp-redundant constant precompute (shuffles, no barriers)
//   g_j = sum_{t>=2} W1[j,t]*Wout[t],  gb = sum_{t>=2} b1[t]*Wout[t]
// then per-node collapse:
//   h0 = x·W1[:,0]+b1[0]; h1 = x·W1[:,1]+b1[1]; T = x·g + gb
//   A = w0*h0 + w1*h1;  B = w1*h0 - w0*h1
//   g_node[i] = (A, B, T);  out[i] = A + T + bout
// ---------------------------------------------------------------------------
__global__ void node_kernel(const float4* __restrict__ x4,
                            const float* __restrict__ W1,
                            const float* __restrict__ b1,
                            const float* __restrict__ Wout,
                            const float* __restrict__ bout,
                            float* __restrict__ out, int n, int hidden) {
    int lane = threadIdx.x & 31;

    float s0 = 0.f, s1 = 0.f, s2 = 0.f, s3 = 0.f, s4 = 0.f;
    for (int t = lane; t < hidden; t += 32) {
        float wk = __ldg(Wout + t);
        float mask = (t >= 2) ? wk : 0.f;
        s0 = fmaf(mask, __ldg(W1 + 0 * hidden + t), s0);
        s1 = fmaf(mask, __ldg(W1 + 1 * hidden + t), s1);
        s2 = fmaf(mask, __ldg(W1 + 2 * hidden + t), s2);
        s3 = fmaf(mask, __ldg(W1 + 3 * hidden + t), s3);
        s4 = fmaf(mask, __ldg(b1 + t), s4);
    }
    #pragma unroll
    for (int off = 16; off > 0; off >>= 1) {
        s0 += __shfl_xor_sync(0xFFFFFFFF, s0, off);
        s1 += __shfl_xor_sync(0xFFFFFFFF, s1, off);
        s2 += __shfl_xor_sync(0xFFFFFFFF, s2, off);
        s3 += __shfl_xor_sync(0xFFFFFFFF, s3, off);
        s4 += __shfl_xor_sync(0xFFFFFFFF, s4, off);
    }

    int i = blockIdx.x * blockDim.x + threadIdx.x;
    if (i >= n) return;

    float c0  = __ldg(Wout + 0), c1 = __ldg(Wout + 1);
    float a0  = __ldg(W1 + 0 * hidden),     a1 = __ldg(W1 + 1 * hidden);
    float a2  = __ldg(W1 + 2 * hidden),     a3 = __ldg(W1 + 3 * hidden);
    float d0  = __ldg(W1 + 0 * hidden + 1), d1 = __ldg(W1 + 1 * hidden + 1);
    float d2  = __ldg(W1 + 2 * hidden + 1), d3 = __ldg(W1 + 3 * hidden + 1);
    float b10 = __ldg(b1 + 0), b11 = __ldg(b1 + 1);
    float bo  = __ldg(bout);

    float4 xv = x4[i];
    float h0 = fmaf(xv.x, a0, fmaf(xv.y, a1, fmaf(xv.z, a2, fmaf(xv.w, a3, b10))));
    float h1 = fmaf(xv.x, d0, fmaf(xv.y, d1, fmaf(xv.z, d2, fmaf(xv.w, d3, b11))));
    float T  = fmaf(xv.x, s0, fmaf(xv.y, s1, fmaf(xv.z, s2, fmaf(xv.w, s3, s4))));
    float A  = fmaf(h0, c0, h1 * c1);
    float B  = fmaf(h0, c1, -h1 * c0);

    g_node[i] = make_float4(A, B, T, 0.f);
    out[i] = A + T + bo;
}

// ---------------------------------------------------------------------------
// edge_kernel: one edge per thread, block=512 (fewer blocks, less scheduling
// churn; 22 regs -> 4 blocks/SM = 64 warps, full RF occupancy).
// Per edge e=(u,v), phase p:
//   out[v] += c*A_u + s*B_u + T_u
//   out[u] += c*A_v - s*B_v + T_v
// ---------------------------------------------------------------------------
__global__ void __launch_bounds__(512, 4)
edge_kernel(const int2* __restrict__ edges,
            const float* __restrict__ phases,
            float* __restrict__ out, int m) {
    int e = blockIdx.x * blockDim.x + threadIdx.x;
    if (e >= m) return;
    int2 ed = edges[e];
    float p = phases[e];
    float4 nu = __ldg(&g_node[ed.x]);   // source features
    float4 nv = __ldg(&g_node[ed.y]);   // dest features
    float s, c;
    __sincosf(p, &s, &c);
    atomicAdd(out + ed.y, fmaf(c, nu.x, fmaf(s,  nu.y, nu.z)));
    atomicAdd(out + ed.x, fmaf(c, nv.x, fmaf(-s, nv.y, nv.z)));
}

extern "C" void kernel_launch(void* const* d_in, const int* in_sizes, int n_in,
                              void* d_out, int out_size) {
    const float* x      = (const float*)d_in[0];
    const int*   edges  = (const int*)  d_in[1];
    const float* W1     = (const float*)d_in[2];
    const float* b1     = (const float*)d_in[3];
    const float* phases = (const float*)d_in[4];
    const float* Wout   = (const float*)d_in[5];
    const float* bout   = (const float*)d_in[6];
    float* out = (float*)d_out;

    int hidden = in_sizes[3];          // 64
    int n = in_sizes[0] / 4;           // nodes (IN_DIM = 4)
    int m = in_sizes[1] / 2;           // edges

    node_kernel<<<(n + 255) / 256, 256>>>((const float4*)x, W1, b1, Wout, bout,
                                          out, n, hidden);

    edge_kernel<<<(m + 511) / 512, 512>>>((const int2*)edges, phases, out, m);
}